// round 12
// baseline (speedup 1.0000x reference)
#include <cuda_runtime.h>
#include <cuda_bf16.h>
#include <mma.h>
#include <math.h>

using namespace nvcuda;

#define Bb   2
#define Nn   2048
#define Cc   1024
#define Hh   16
#define HDd  64
#define ROWS (Bb * Nn)          // 4096
#define LNEPS 1e-5f

typedef __nv_bfloat16 bf16;

// f32 scratch (QKV GEMM output for Q/K; LN reads these)
__device__ float g_q[Bb * Hh * Nn * HDd];
__device__ float g_k[Bb * Hh * Nn * HDd];

// bf16 hi/lo scratch as float4 arrays; ONLY referenced from device code.
__device__ float4 g_xh4[524288],  g_xl4[524288];    // x        [4096][1024]
__device__ float4 g_wqh4[393216], g_wql4[393216];   // w_qkv    [1024][3072]
__device__ float4 g_wph4[131072], g_wpl4[131072];   // w_proj   [1024][1024]
__device__ float4 g_qh4[524288],  g_ql4[524288];    // Q (post-LN)  [bh][n][d]
__device__ float4 g_kh4[524288],  g_kl4[524288];    // K (post-LN)  [bh][n][d]
__device__ float4 g_vh4[524288],  g_vl4[524288];    // V            [bh][n][d]
__device__ float4 g_oh4[524288],  g_ol4[524288];    // attn out, row-major [4096][1024]

__device__ __forceinline__ void split_bf16(float f, bf16& hi, bf16& lo) {
    hi = __float2bfloat16(f);
    lo = __float2bfloat16(f - __bfloat162float(hi));
}

// ---------------------------------------------------------------------------
// conv: f32 -> bf16 hi/lo. which: 0=x, 1=w_qkv, 2=w_proj
// ---------------------------------------------------------------------------
__global__ void conv_kernel(const float* src, int which) {
    float4* dh4 = (which == 0) ? g_xh4 : (which == 1) ? g_wqh4 : g_wph4;
    float4* dl4 = (which == 0) ? g_xl4 : (which == 1) ? g_wql4 : g_wpl4;
    int i = blockIdx.x * blockDim.x + threadIdx.x;
    float4 a = *(const float4*)(src + (size_t)i * 8);
    float4 b = *(const float4*)(src + (size_t)i * 8 + 4);
    float v[8] = {a.x, a.y, a.z, a.w, b.x, b.y, b.z, b.w};
    __nv_bfloat162* dh = (__nv_bfloat162*)(dh4 + i);
    __nv_bfloat162* dl = (__nv_bfloat162*)(dl4 + i);
    #pragma unroll
    for (int p = 0; p < 4; p++) {
        bf16 h0, l0, h1, l1;
        split_bf16(v[2 * p], h0, l0);
        split_bf16(v[2 * p + 1], h1, l1);
        __nv_bfloat162 hh; hh.x = h0; hh.y = h1;
        __nv_bfloat162 ll; ll.x = l0; ll.y = l1;
        dh[p] = hh;
        dl[p] = ll;
    }
}

// ---------------------------------------------------------------------------
// bf16 hi/lo wmma GEMM, BK=32, register-prefetch double buffering.
// 128x128 tile, 256 threads, 8 warps (2x4), warp tile 64x32.
// ---------------------------------------------------------------------------
#define AS2 40
#define BS2 136
#define SLD 20

#define OFF_ASH 0
#define OFF_ASL 640
#define OFF_BSH 1280
#define OFF_BSL 1824
#define OFF_ST  2368
#define POOL_SZ 3008

__global__ void gemm_wmma(const float* bias, float* out, int mode) {
    __shared__ float4 pool[POOL_SZ];
    bf16*  Ash = (bf16*)(pool + OFF_ASH);
    bf16*  Asl = (bf16*)(pool + OFF_ASL);
    bf16*  Bsh = (bf16*)(pool + OFF_BSH);
    bf16*  Bsl = (bf16*)(pool + OFF_BSL);
    float* St  = (float*)(pool + OFF_ST);

    const bf16* Ah = (const bf16*)(mode ? g_xh4 : g_oh4);
    const bf16* Al = (const bf16*)(mode ? g_xl4 : g_ol4);
    const bf16* Wh = (const bf16*)(mode ? g_wqh4 : g_wph4);
    const bf16* Wl = (const bf16*)(mode ? g_wql4 : g_wpl4);
    const int ldw  = mode ? 3 * Cc : Cc;

    const int tid   = threadIdx.x;
    const int wid   = tid >> 5;
    const int lane  = tid & 31;
    const int warpM = wid >> 2;
    const int warpN = wid & 3;
    const int gr    = blockIdx.y * 128;
    const int gc    = blockIdx.x * 128;

    int aRow[2], aCol[2], bRow[2], bCol[2];
    #pragma unroll
    for (int p = 0; p < 2; p++) {
        int idx = tid + p * 256;
        aRow[p] = idx >> 2;  aCol[p] = (idx & 3) * 8;
        bRow[p] = idx >> 4;  bCol[p] = (idx & 15) * 8;
    }

    wmma::fragment<wmma::accumulator, 16, 16, 16, float> cf[4][2];
    #pragma unroll
    for (int mt = 0; mt < 4; mt++)
        #pragma unroll
        for (int nt = 0; nt < 2; nt++) wmma::fill_fragment(cf[mt][nt], 0.0f);

    // prologue: prefetch k0 = 0
    uint4 rAh[2], rAl[2], rBh[2], rBl[2];
    #pragma unroll
    for (int p = 0; p < 2; p++) {
        size_t sa = (size_t)(gr + aRow[p]) * Cc + aCol[p];
        size_t sb = (size_t)bRow[p] * ldw + gc + bCol[p];
        rAh[p] = *(const uint4*)(Ah + sa);
        rAl[p] = *(const uint4*)(Al + sa);
        rBh[p] = *(const uint4*)(Wh + sb);
        rBl[p] = *(const uint4*)(Wl + sb);
    }

    for (int k0 = 0; k0 < Cc; k0 += 32) {
        // commit staged registers to smem
        #pragma unroll
        for (int p = 0; p < 2; p++) {
            *(uint4*)&Ash[aRow[p] * AS2 + aCol[p]] = rAh[p];
            *(uint4*)&Asl[aRow[p] * AS2 + aCol[p]] = rAl[p];
            *(uint4*)&Bsh[bRow[p] * BS2 + bCol[p]] = rBh[p];
            *(uint4*)&Bsl[bRow[p] * BS2 + bCol[p]] = rBl[p];
        }
        __syncthreads();

        // prefetch next K-tile (overlaps with MMA below)
        if (k0 + 32 < Cc) {
            #pragma unroll
            for (int p = 0; p < 2; p++) {
                size_t sa = (size_t)(gr + aRow[p]) * Cc + (k0 + 32) + aCol[p];
                size_t sb = (size_t)(k0 + 32 + bRow[p]) * ldw + gc + bCol[p];
                rAh[p] = *(const uint4*)(Ah + sa);
                rAl[p] = *(const uint4*)(Al + sa);
                rBh[p] = *(const uint4*)(Wh + sb);
                rBl[p] = *(const uint4*)(Wl + sb);
            }
        }

        #pragma unroll
        for (int ks = 0; ks < 2; ks++) {
            wmma::fragment<wmma::matrix_a, 16, 16, 16, bf16, wmma::row_major> ah[4], al[4];
            wmma::fragment<wmma::matrix_b, 16, 16, 16, bf16, wmma::row_major> bh[2], bl[2];
            #pragma unroll
            for (int mt = 0; mt < 4; mt++) {
                wmma::load_matrix_sync(ah[mt], &Ash[(warpM * 64 + mt * 16) * AS2 + ks * 16], AS2);
                wmma::load_matrix_sync(al[mt], &Asl[(warpM * 64 + mt * 16) * AS2 + ks * 16], AS2);
            }
            #pragma unroll
            for (int nt = 0; nt < 2; nt++) {
                wmma::load_matrix_sync(bh[nt], &Bsh[(ks * 16) * BS2 + warpN * 32 + nt * 16], BS2);
                wmma::load_matrix_sync(bl[nt], &Bsl[(ks * 16) * BS2 + warpN * 32 + nt * 16], BS2);
            }
            #pragma unroll
            for (int mt = 0; mt < 4; mt++)
                #pragma unroll
                for (int nt = 0; nt < 2; nt++) {
                    wmma::mma_sync(cf[mt][nt], ah[mt], bh[nt], cf[mt][nt]);
                    wmma::mma_sync(cf[mt][nt], ah[mt], bl[nt], cf[mt][nt]);
                    wmma::mma_sync(cf[mt][nt], al[mt], bh[nt], cf[mt][nt]);
                }
        }
        __syncthreads();
    }

    bf16* vhE = (bf16*)g_vh4;
    bf16* vlE = (bf16*)g_vl4;
    float* stg = &St[wid * 16 * SLD];
    #pragma unroll
    for (int mt = 0; mt < 4; mt++) {
        #pragma unroll
        for (int nt = 0; nt < 2; nt++) {
            wmma::store_matrix_sync(stg, cf[mt][nt], SLD, wmma::mem_row_major);
            __syncwarp();
            #pragma unroll
            for (int i = 0; i < 8; i++) {
                int e = lane * 8 + i;
                int r = e >> 4, c = e & 15;
                int row = gr + warpM * 64 + mt * 16 + r;
                int col = gc + warpN * 32 + nt * 16 + c;
                float v = stg[r * SLD + c] + bias[col];
                if (mode) {
                    int b  = row / Nn, n = row % Nn;
                    int wh = col >> 10;
                    int ci = col & 1023;
                    int h  = ci >> 6, d = ci & 63;
                    size_t o = ((size_t)(b * Hh + h) * Nn + n) * HDd + d;
                    if (wh == 0)      g_q[o] = v;
                    else if (wh == 1) g_k[o] = v;
                    else {
                        bf16 hh, ll;
                        split_bf16(v, hh, ll);
                        vhE[o] = hh;
                        vlE[o] = ll;
                    }
                } else {
                    out[(size_t)row * Cc + col] = v;
                }
            }
            __syncwarp();
        }
    }
}

// ---------------------------------------------------------------------------
// LayerNorm over HD=64, one warp per row; emits bf16 hi/lo (Q scaled).
// ---------------------------------------------------------------------------
__global__ void ln_kernel(const float* __restrict__ gq, const float* __restrict__ beq,
                          const float* __restrict__ gk, const float* __restrict__ bek) {
    const int R = Bb * Hh * Nn;
    int warp = (blockIdx.x * blockDim.x + threadIdx.x) >> 5;
    int lane = threadIdx.x & 31;
    if (warp >= 2 * R) return;

    bool isq = warp < R;
    const float* buf = isq ? g_q : g_k;
    bf16* outh = (bf16*)(isq ? g_qh4 : g_kh4);
    bf16* outl = (bf16*)(isq ? g_ql4 : g_kl4);
    const float* gam = isq ? gq  : gk;
    const float* bet = isq ? beq : bek;
    float scale      = isq ? 0.125f : 1.0f;
    int row = isq ? warp : warp - R;

    float v0 = buf[(size_t)row * HDd + lane];
    float v1 = buf[(size_t)row * HDd + 32 + lane];
    float s  = v0 + v1;
    float ss = v0 * v0 + v1 * v1;
    #pragma unroll
    for (int off = 16; off; off >>= 1) {
        s  += __shfl_xor_sync(0xffffffffu, s,  off);
        ss += __shfl_xor_sync(0xffffffffu, ss, off);
    }
    float mu  = s * (1.0f / HDd);
    float var = ss * (1.0f / HDd) - mu * mu;
    float inv = rsqrtf(var + LNEPS);
    float r0 = ((v0 - mu) * inv * gam[lane]      + bet[lane])      * scale;
    float r1 = ((v1 - mu) * inv * gam[lane + 32] + bet[lane + 32]) * scale;
    bf16 h, l;
    split_bf16(r0, h, l);
    outh[(size_t)row * HDd + lane] = h;
    outl[(size_t)row * HDd + lane] = l;
    split_bf16(r1, h, l);
    outh[(size_t)row * HDd + 32 + lane] = h;
    outl[(size_t)row * HDd + 32 + lane] = l;
}

// ---------------------------------------------------------------------------
// Flash attention, wmma bf16 hi/lo. No online max (|s| <= 8 deterministically:
// |q|=1 after LN*HD^-0.5, |k|=8). PV accumulators persist in fragments across
// all KV tiles (no rescale needed). KV tiles register-prefetched.
// ---------------------------------------------------------------------------
#define BQS 72    // bf16 tile stride
#define FQS 68    // f32 tile stride
#define O_QH 0
#define O_QL 4608
#define O_KH 9216
#define O_KL 11520
#define O_VH 13824
#define O_VL 16128
#define O_PH 18432
#define O_PL 23040
#define O_SS 27648
#define O_LR 36352
#define ATTN_FLOATS 36480
#define ATTN_SMEM (ATTN_FLOATS * 4)    // 145920 B

__global__ void attn_wmma() {
    extern __shared__ float sm[];
    bf16*  Qh = (bf16*)(sm + O_QH);
    bf16*  Ql = (bf16*)(sm + O_QL);
    bf16*  Kh = (bf16*)(sm + O_KH);
    bf16*  Kl = (bf16*)(sm + O_KL);
    bf16*  Vh = (bf16*)(sm + O_VH);
    bf16*  Vl = (bf16*)(sm + O_VL);
    bf16*  Ph = (bf16*)(sm + O_PH);
    bf16*  Pl = (bf16*)(sm + O_PL);
    float* Ss = sm + O_SS;
    float* lrow = sm + O_LR;

    const int tid  = threadIdx.x;
    const int w    = tid >> 5;
    const int lane = tid & 31;
    const int bh   = blockIdx.y;
    const int q0   = blockIdx.x * 128;

    // stage Q (copy)
    const bf16* QhG = (const bf16*)g_qh4 + ((size_t)bh * Nn + q0) * HDd;
    const bf16* QlG = (const bf16*)g_ql4 + ((size_t)bh * Nn + q0) * HDd;
    #pragma unroll
    for (int i = 0; i < 4; i++) {
        int idx = tid + i * 256;
        int row = idx >> 3, c8 = idx & 7;
        *(uint4*)&Qh[row * BQS + c8 * 8] = *(const uint4*)(QhG + (size_t)row * HDd + c8 * 8);
        *(uint4*)&Ql[row * BQS + c8 * 8] = *(const uint4*)(QlG + (size_t)row * HDd + c8 * 8);
    }
    if (tid < 128) lrow[tid] = 0.0f;

    const int myrow = w * 16 + (lane >> 1);
    const int half  = lane & 1;

    // persistent PV accumulators (16 q-rows x 64 d per warp)
    wmma::fragment<wmma::accumulator, 16, 16, 16, float> ovf[4];
    #pragma unroll
    for (int nt = 0; nt < 4; nt++) wmma::fill_fragment(ovf[nt], 0.0f);

    // KV prefetch setup
    int kvRow[2], kvCol[2];
    #pragma unroll
    for (int p = 0; p < 2; p++) {
        int idx = tid + p * 256;
        kvRow[p] = idx >> 3;
        kvCol[p] = (idx & 7) * 8;
    }
    const bf16* KhB = (const bf16*)g_kh4 + (size_t)bh * Nn * HDd;
    const bf16* KlB = (const bf16*)g_kl4 + (size_t)bh * Nn * HDd;
    const bf16* VhB = (const bf16*)g_vh4 + (size_t)bh * Nn * HDd;
    const bf16* VlB = (const bf16*)g_vl4 + (size_t)bh * Nn * HDd;
    uint4 rKh[2], rKl[2], rVh[2], rVl[2];
    #pragma unroll
    for (int p = 0; p < 2; p++) {
        size_t src = (size_t)kvRow[p] * HDd + kvCol[p];
        rKh[p] = *(const uint4*)(KhB + src);
        rKl[p] = *(const uint4*)(KlB + src);
        rVh[p] = *(const uint4*)(VhB + src);
        rVl[p] = *(const uint4*)(VlB + src);
    }

    for (int kt = 0; kt < Nn / 64; kt++) {
        __syncthreads();           // prior tile's readers done
        #pragma unroll
        for (int p = 0; p < 2; p++) {
            *(uint4*)&Kh[kvRow[p] * BQS + kvCol[p]] = rKh[p];
            *(uint4*)&Kl[kvRow[p] * BQS + kvCol[p]] = rKl[p];
            *(uint4*)&Vh[kvRow[p] * BQS + kvCol[p]] = rVh[p];
            *(uint4*)&Vl[kvRow[p] * BQS + kvCol[p]] = rVl[p];
        }
        __syncthreads();

        // prefetch next KV tile (overlaps with compute below)
        if (kt + 1 < Nn / 64) {
            size_t toff = (size_t)(kt + 1) * 64 * HDd;
            #pragma unroll
            for (int p = 0; p < 2; p++) {
                size_t src = toff + (size_t)kvRow[p] * HDd + kvCol[p];
                rKh[p] = *(const uint4*)(KhB + src);
                rKl[p] = *(const uint4*)(KlB + src);
                rVh[p] = *(const uint4*)(VhB + src);
                rVl[p] = *(const uint4*)(VlB + src);
            }
        }

        // ---- S = Q . K^T ----
        {
            wmma::fragment<wmma::accumulator, 16, 16, 16, float> sf[4];
            #pragma unroll
            for (int nt = 0; nt < 4; nt++) wmma::fill_fragment(sf[nt], 0.0f);
            #pragma unroll
            for (int ks = 0; ks < 4; ks++) {
                wmma::fragment<wmma::matrix_a, 16, 16, 16, bf16, wmma::row_major> ah, al;
                wmma::load_matrix_sync(ah, &Qh[(w * 16) * BQS + ks * 16], BQS);
                wmma::load_matrix_sync(al, &Ql[(w * 16) * BQS + ks * 16], BQS);
                #pragma unroll
                for (int nt = 0; nt < 4; nt++) {
                    wmma::fragment<wmma::matrix_b, 16, 16, 16, bf16, wmma::col_major> bhf, blf;
                    wmma::load_matrix_sync(bhf, &Kh[(nt * 16) * BQS + ks * 16], BQS);
                    wmma::load_matrix_sync(blf, &Kl[(nt * 16) * BQS + ks * 16], BQS);
                    wmma::mma_sync(sf[nt], ah, bhf, sf[nt]);
                    wmma::mma_sync(sf[nt], ah, blf, sf[nt]);
                    wmma::mma_sync(sf[nt], al, bhf, sf[nt]);
                }
            }
            #pragma unroll
            for (int nt = 0; nt < 4; nt++)
                wmma::store_matrix_sync(&Ss[(w * 16) * FQS + nt * 16], sf[nt], FQS, wmma::mem_row_major);
            __syncwarp();
        }

        // ---- softmax numerator: P = exp(S); accumulate row sums ----
        {
            float* srow = &Ss[myrow * FQS + half * 32];
            float sum = 0.0f;
            #pragma unroll
            for (int j = 0; j < 32; j++) {
                float e = __expf(srow[j]);
                sum += e;
                bf16 h, l;
                split_bf16(e, h, l);
                Ph[myrow * BQS + half * 32 + j] = h;
                Pl[myrow * BQS + half * 32 + j] = l;
            }
            sum += __shfl_xor_sync(0xffffffffu, sum, 1);
            if (half == 0) lrow[myrow] += sum;
            __syncwarp();
        }

        // ---- PV: accumulate into persistent fragments ----
        #pragma unroll
        for (int ks = 0; ks < 4; ks++) {
            wmma::fragment<wmma::matrix_a, 16, 16, 16, bf16, wmma::row_major> ah, al;
            wmma::load_matrix_sync(ah, &Ph[(w * 16) * BQS + ks * 16], BQS);
            wmma::load_matrix_sync(al, &Pl[(w * 16) * BQS + ks * 16], BQS);
            #pragma unroll
            for (int nt = 0; nt < 4; nt++) {
                wmma::fragment<wmma::matrix_b, 16, 16, 16, bf16, wmma::row_major> bhf, blf;
                wmma::load_matrix_sync(bhf, &Vh[(ks * 16) * BQS + nt * 16], BQS);
                wmma::load_matrix_sync(blf, &Vl[(ks * 16) * BQS + nt * 16], BQS);
                wmma::mma_sync(ovf[nt], ah, bhf, ovf[nt]);
                wmma::mma_sync(ovf[nt], ah, blf, ovf[nt]);
                wmma::mma_sync(ovf[nt], al, bhf, ovf[nt]);
            }
        }
    }

    // epilogue: dump output fragments, normalize, write hi/lo row-major
    #pragma unroll
    for (int nt = 0; nt < 4; nt++)
        wmma::store_matrix_sync(&Ss[(w * 16) * FQS + nt * 16], ovf[nt], FQS, wmma::mem_row_major);
    __syncthreads();

    {
        int b = bh >> 4, h = bh & 15;     // bh = b*Hh + h
        bf16* ohE = (bf16*)g_oh4;
        bf16* olE = (bf16*)g_ol4;
        for (int i = 0; i < 32; i++) {
            int idx = tid + i * 256;       // 0..8191
            int row = idx >> 6, d = idx & 63;
            float v = Ss[row * FQS + d] / lrow[row];
            size_t o = (size_t)(b * Nn + q0 + row) * Cc + h * HDd + d;
            bf16 hh, ll;
            split_bf16(v, hh, ll);
            ohE[o] = hh;
            olE[o] = ll;
        }
    }
}

// ---------------------------------------------------------------------------
extern "C" void kernel_launch(void* const* d_in, const int* in_sizes, int n_in,
                              void* d_out, int out_size) {
    const float* x      = (const float*)d_in[0];
    const float* w_qkv  = (const float*)d_in[1];
    const float* b_qkv  = (const float*)d_in[2];
    const float* gq     = (const float*)d_in[3];
    const float* beq    = (const float*)d_in[4];
    const float* gk     = (const float*)d_in[5];
    const float* bek    = (const float*)d_in[6];
    const float* w_proj = (const float*)d_in[7];
    const float* b_proj = (const float*)d_in[8];
    float* out = (float*)d_out;

    cudaFuncSetAttribute(attn_wmma, cudaFuncAttributeMaxDynamicSharedMemorySize, ATTN_SMEM);

    conv_kernel<<<2048, 256>>>(x,      0);
    conv_kernel<<<1536, 256>>>(w_qkv,  1);
    conv_kernel<<<512,  256>>>(w_proj, 2);
    gemm_wmma<<<dim3(3 * Cc / 128, ROWS / 128), 256>>>(b_qkv, nullptr, 1);
    ln_kernel<<<(2 * Bb * Hh * Nn) / 8, 256>>>(gq, beq, gk, bek);
    attn_wmma<<<dim3(Nn / 128, Bb * Hh), 256, ATTN_SMEM>>>();
    gemm_wmma<<<dim3(Cc / 128, ROWS / 128), 256>>>(b_proj, out, 0);
}

// round 13
// speedup vs baseline: 1.1124x; 1.1124x over previous
#include <cuda_runtime.h>
#include <cuda_bf16.h>
#include <mma.h>
#include <math.h>

using namespace nvcuda;

#define Bb   2
#define Nn   2048
#define Cc   1024
#define Hh   16
#define HDd  64
#define ROWS (Bb * Nn)          // 4096
#define LNEPS 1e-5f

typedef __nv_bfloat16 bf16;

// f32 scratch (QKV GEMM output for Q/K; LN reads these)
__device__ float g_q[Bb * Hh * Nn * HDd];
__device__ float g_k[Bb * Hh * Nn * HDd];

// bf16 hi/lo scratch as float4 arrays; ONLY referenced from device code.
__device__ float4 g_xh4[524288],  g_xl4[524288];    // x        [4096][1024]
__device__ float4 g_wqh4[393216], g_wql4[393216];   // w_qkv    [1024][3072]
__device__ float4 g_wph4[131072], g_wpl4[131072];   // w_proj   [1024][1024]
__device__ float4 g_qh4[524288],  g_ql4[524288];    // Q (post-LN)  [bh][n][d]
__device__ float4 g_kh4[524288],  g_kl4[524288];    // K (post-LN)  [bh][n][d]
__device__ float4 g_vh4[524288],  g_vl4[524288];    // V            [bh][n][d]
__device__ float4 g_oh4[524288],  g_ol4[524288];    // attn out, row-major [4096][1024]

__device__ __forceinline__ void split_bf16(float f, bf16& hi, bf16& lo) {
    hi = __float2bfloat16(f);
    lo = __float2bfloat16(f - __bfloat162float(hi));
}

// ---------------------------------------------------------------------------
// conv: f32 -> bf16 hi/lo. which: 0=x, 1=w_qkv, 2=w_proj
// ---------------------------------------------------------------------------
__global__ void conv_kernel(const float* src, int which) {
    float4* dh4 = (which == 0) ? g_xh4 : (which == 1) ? g_wqh4 : g_wph4;
    float4* dl4 = (which == 0) ? g_xl4 : (which == 1) ? g_wql4 : g_wpl4;
    int i = blockIdx.x * blockDim.x + threadIdx.x;
    float4 a = *(const float4*)(src + (size_t)i * 8);
    float4 b = *(const float4*)(src + (size_t)i * 8 + 4);
    float v[8] = {a.x, a.y, a.z, a.w, b.x, b.y, b.z, b.w};
    __nv_bfloat162* dh = (__nv_bfloat162*)(dh4 + i);
    __nv_bfloat162* dl = (__nv_bfloat162*)(dl4 + i);
    #pragma unroll
    for (int p = 0; p < 4; p++) {
        bf16 h0, l0, h1, l1;
        split_bf16(v[2 * p], h0, l0);
        split_bf16(v[2 * p + 1], h1, l1);
        __nv_bfloat162 hh; hh.x = h0; hh.y = h1;
        __nv_bfloat162 ll; ll.x = l0; ll.y = l1;
        dh[p] = hh;
        dl[p] = ll;
    }
}

// ---------------------------------------------------------------------------
// bf16 hi/lo wmma GEMM, BK=32, copy-only staging, 2 CTAs/SM via launch bounds.
// 128x128 tile, 256 threads, 8 warps (2x4), warp tile 64x32.
// ---------------------------------------------------------------------------
#define AS2 40
#define BS2 136
#define SLD 20

#define OFF_ASH 0
#define OFF_ASL 640
#define OFF_BSH 1280
#define OFF_BSL 1824
#define OFF_ST  2368
#define POOL_SZ 3008

__global__ void __launch_bounds__(256, 2) gemm_wmma(const float* bias, float* out, int mode) {
    __shared__ float4 pool[POOL_SZ];
    bf16*  Ash = (bf16*)(pool + OFF_ASH);
    bf16*  Asl = (bf16*)(pool + OFF_ASL);
    bf16*  Bsh = (bf16*)(pool + OFF_BSH);
    bf16*  Bsl = (bf16*)(pool + OFF_BSL);
    float* St  = (float*)(pool + OFF_ST);

    const bf16* Ah = (const bf16*)(mode ? g_xh4 : g_oh4);
    const bf16* Al = (const bf16*)(mode ? g_xl4 : g_ol4);
    const bf16* Wh = (const bf16*)(mode ? g_wqh4 : g_wph4);
    const bf16* Wl = (const bf16*)(mode ? g_wql4 : g_wpl4);
    const int ldw  = mode ? 3 * Cc : Cc;

    const int tid   = threadIdx.x;
    const int wid   = tid >> 5;
    const int lane  = tid & 31;
    const int warpM = wid >> 2;
    const int warpN = wid & 3;
    const int gr    = blockIdx.y * 128;
    const int gc    = blockIdx.x * 128;

    wmma::fragment<wmma::accumulator, 16, 16, 16, float> cf[4][2];
    #pragma unroll
    for (int mt = 0; mt < 4; mt++)
        #pragma unroll
        for (int nt = 0; nt < 2; nt++) wmma::fill_fragment(cf[mt][nt], 0.0f);

    for (int k0 = 0; k0 < Cc; k0 += 32) {
        // A tiles 128x32 (hi+lo): 512 uint4 each, 2 per thread
        #pragma unroll
        for (int p = 0; p < 2; p++) {
            int idx = tid + p * 256;
            int row = idx >> 2, c4 = idx & 3;
            size_t src = (size_t)(gr + row) * Cc + k0 + c4 * 8;
            *(uint4*)&Ash[row * AS2 + c4 * 8] = *(const uint4*)(Ah + src);
            *(uint4*)&Asl[row * AS2 + c4 * 8] = *(const uint4*)(Al + src);
        }
        // B tiles 32x128 (hi+lo): 512 uint4 each, 2 per thread
        #pragma unroll
        for (int p = 0; p < 2; p++) {
            int idx = tid + p * 256;
            int k = idx >> 4, n4 = idx & 15;
            size_t src = (size_t)(k0 + k) * ldw + gc + n4 * 8;
            *(uint4*)&Bsh[k * BS2 + n4 * 8] = *(const uint4*)(Wh + src);
            *(uint4*)&Bsl[k * BS2 + n4 * 8] = *(const uint4*)(Wl + src);
        }
        __syncthreads();

        #pragma unroll
        for (int ks = 0; ks < 2; ks++) {
            wmma::fragment<wmma::matrix_a, 16, 16, 16, bf16, wmma::row_major> ah[4], al[4];
            wmma::fragment<wmma::matrix_b, 16, 16, 16, bf16, wmma::row_major> bh[2], bl[2];
            #pragma unroll
            for (int mt = 0; mt < 4; mt++) {
                wmma::load_matrix_sync(ah[mt], &Ash[(warpM * 64 + mt * 16) * AS2 + ks * 16], AS2);
                wmma::load_matrix_sync(al[mt], &Asl[(warpM * 64 + mt * 16) * AS2 + ks * 16], AS2);
            }
            #pragma unroll
            for (int nt = 0; nt < 2; nt++) {
                wmma::load_matrix_sync(bh[nt], &Bsh[(ks * 16) * BS2 + warpN * 32 + nt * 16], BS2);
                wmma::load_matrix_sync(bl[nt], &Bsl[(ks * 16) * BS2 + warpN * 32 + nt * 16], BS2);
            }
            #pragma unroll
            for (int mt = 0; mt < 4; mt++)
                #pragma unroll
                for (int nt = 0; nt < 2; nt++) {
                    wmma::mma_sync(cf[mt][nt], ah[mt], bh[nt], cf[mt][nt]);
                    wmma::mma_sync(cf[mt][nt], ah[mt], bl[nt], cf[mt][nt]);
                    wmma::mma_sync(cf[mt][nt], al[mt], bh[nt], cf[mt][nt]);
                }
        }
        __syncthreads();
    }

    bf16* vhE = (bf16*)g_vh4;
    bf16* vlE = (bf16*)g_vl4;
    float* stg = &St[wid * 16 * SLD];
    #pragma unroll
    for (int mt = 0; mt < 4; mt++) {
        #pragma unroll
        for (int nt = 0; nt < 2; nt++) {
            wmma::store_matrix_sync(stg, cf[mt][nt], SLD, wmma::mem_row_major);
            __syncwarp();
            #pragma unroll
            for (int i = 0; i < 8; i++) {
                int e = lane * 8 + i;
                int r = e >> 4, c = e & 15;
                int row = gr + warpM * 64 + mt * 16 + r;
                int col = gc + warpN * 32 + nt * 16 + c;
                float v = stg[r * SLD + c] + bias[col];
                if (mode) {
                    int b  = row / Nn, n = row % Nn;
                    int wh = col >> 10;
                    int ci = col & 1023;
                    int h  = ci >> 6, d = ci & 63;
                    size_t o = ((size_t)(b * Hh + h) * Nn + n) * HDd + d;
                    if (wh == 0)      g_q[o] = v;
                    else if (wh == 1) g_k[o] = v;
                    else {
                        bf16 hh, ll;
                        split_bf16(v, hh, ll);
                        vhE[o] = hh;
                        vlE[o] = ll;
                    }
                } else {
                    out[(size_t)row * Cc + col] = v;
                }
            }
            __syncwarp();
        }
    }
}

// ---------------------------------------------------------------------------
// LayerNorm over HD=64, one warp per row; emits bf16 hi/lo (Q scaled).
// ---------------------------------------------------------------------------
__global__ void ln_kernel(const float* __restrict__ gq, const float* __restrict__ beq,
                          const float* __restrict__ gk, const float* __restrict__ bek) {
    const int R = Bb * Hh * Nn;
    int warp = (blockIdx.x * blockDim.x + threadIdx.x) >> 5;
    int lane = threadIdx.x & 31;
    if (warp >= 2 * R) return;

    bool isq = warp < R;
    const float* buf = isq ? g_q : g_k;
    bf16* outh = (bf16*)(isq ? g_qh4 : g_kh4);
    bf16* outl = (bf16*)(isq ? g_ql4 : g_kl4);
    const float* gam = isq ? gq  : gk;
    const float* bet = isq ? beq : bek;
    float scale      = isq ? 0.125f : 1.0f;
    int row = isq ? warp : warp - R;

    float v0 = buf[(size_t)row * HDd + lane];
    float v1 = buf[(size_t)row * HDd + 32 + lane];
    float s  = v0 + v1;
    float ss = v0 * v0 + v1 * v1;
    #pragma unroll
    for (int off = 16; off; off >>= 1) {
        s  += __shfl_xor_sync(0xffffffffu, s,  off);
        ss += __shfl_xor_sync(0xffffffffu, ss, off);
    }
    float mu  = s * (1.0f / HDd);
    float var = ss * (1.0f / HDd) - mu * mu;
    float inv = rsqrtf(var + LNEPS);
    float r0 = ((v0 - mu) * inv * gam[lane]      + bet[lane])      * scale;
    float r1 = ((v1 - mu) * inv * gam[lane + 32] + bet[lane + 32]) * scale;
    bf16 h, l;
    split_bf16(r0, h, l);
    outh[(size_t)row * HDd + lane] = h;
    outl[(size_t)row * HDd + lane] = l;
    split_bf16(r1, h, l);
    outh[(size_t)row * HDd + 32 + lane] = h;
    outl[(size_t)row * HDd + 32 + lane] = l;
}

// ---------------------------------------------------------------------------
// Flash attention via wmma bf16 hi/lo (exact R11 version — best known).
// 256 threads (8 warps), Q-block 128, KV tiles 64.
// ---------------------------------------------------------------------------
#define BQS 72    // bf16 tile stride
#define FQS 68    // f32 tile stride
#define O_QH 0
#define O_QL 4608
#define O_KH 9216
#define O_KL 11520
#define O_VH 13824
#define O_VL 16128
#define O_PH 18432
#define O_PL 23040
#define O_SS 27648
#define O_OS 36352
#define O_MR 45056
#define O_LR 45184
#define O_CR 45312
#define ATTN_FLOATS 45440
#define ATTN_SMEM (ATTN_FLOATS * 4)    // 181760 B

__global__ void attn_wmma() {
    extern __shared__ float sm[];
    bf16*  Qh = (bf16*)(sm + O_QH);
    bf16*  Ql = (bf16*)(sm + O_QL);
    bf16*  Kh = (bf16*)(sm + O_KH);
    bf16*  Kl = (bf16*)(sm + O_KL);
    bf16*  Vh = (bf16*)(sm + O_VH);
    bf16*  Vl = (bf16*)(sm + O_VL);
    bf16*  Ph = (bf16*)(sm + O_PH);
    bf16*  Pl = (bf16*)(sm + O_PL);
    float* Ss = sm + O_SS;
    float* Os = sm + O_OS;
    float* mrow = sm + O_MR;
    float* lrow = sm + O_LR;
    float* crow = sm + O_CR;

    const int tid  = threadIdx.x;
    const int w    = tid >> 5;
    const int lane = tid & 31;
    const int bh   = blockIdx.y;
    const int q0   = blockIdx.x * 128;

    // stage Q (copy, 1024 uint4 per half)
    const bf16* QhG = (const bf16*)g_qh4 + ((size_t)bh * Nn + q0) * HDd;
    const bf16* QlG = (const bf16*)g_ql4 + ((size_t)bh * Nn + q0) * HDd;
    #pragma unroll
    for (int i = 0; i < 4; i++) {
        int idx = tid + i * 256;          // 0..1023
        int row = idx >> 3, c8 = idx & 7;
        *(uint4*)&Qh[row * BQS + c8 * 8] = *(const uint4*)(QhG + (size_t)row * HDd + c8 * 8);
        *(uint4*)&Ql[row * BQS + c8 * 8] = *(const uint4*)(QlG + (size_t)row * HDd + c8 * 8);
    }
    for (int i = tid; i < 128 * FQS; i += 256) Os[i] = 0.0f;
    if (tid < 128) { mrow[tid] = -INFINITY; lrow[tid] = 0.0f; }

    const int myrow = w * 16 + (lane >> 1);
    const int half  = lane & 1;

    for (int kt = 0; kt < Nn / 64; kt++) {
        __syncthreads();
        const bf16* KhG = (const bf16*)g_kh4 + ((size_t)bh * Nn + kt * 64) * HDd;
        const bf16* KlG = (const bf16*)g_kl4 + ((size_t)bh * Nn + kt * 64) * HDd;
        const bf16* VhG = (const bf16*)g_vh4 + ((size_t)bh * Nn + kt * 64) * HDd;
        const bf16* VlG = (const bf16*)g_vl4 + ((size_t)bh * Nn + kt * 64) * HDd;
        #pragma unroll
        for (int i = 0; i < 2; i++) {
            int idx = tid + i * 256;      // 0..511
            int row = idx >> 3, c8 = idx & 7;
            size_t src = (size_t)row * HDd + c8 * 8;
            *(uint4*)&Kh[row * BQS + c8 * 8] = *(const uint4*)(KhG + src);
            *(uint4*)&Kl[row * BQS + c8 * 8] = *(const uint4*)(KlG + src);
            *(uint4*)&Vh[row * BQS + c8 * 8] = *(const uint4*)(VhG + src);
            *(uint4*)&Vl[row * BQS + c8 * 8] = *(const uint4*)(VlG + src);
        }
        __syncthreads();

        // ---- S = Q . K^T ----
        {
            wmma::fragment<wmma::accumulator, 16, 16, 16, float> sf[4];
            #pragma unroll
            for (int nt = 0; nt < 4; nt++) wmma::fill_fragment(sf[nt], 0.0f);
            #pragma unroll
            for (int ks = 0; ks < 4; ks++) {
                wmma::fragment<wmma::matrix_a, 16, 16, 16, bf16, wmma::row_major> ah, al;
                wmma::load_matrix_sync(ah, &Qh[(w * 16) * BQS + ks * 16], BQS);
                wmma::load_matrix_sync(al, &Ql[(w * 16) * BQS + ks * 16], BQS);
                #pragma unroll
                for (int nt = 0; nt < 4; nt++) {
                    wmma::fragment<wmma::matrix_b, 16, 16, 16, bf16, wmma::col_major> bhf, blf;
                    wmma::load_matrix_sync(bhf, &Kh[(nt * 16) * BQS + ks * 16], BQS);
                    wmma::load_matrix_sync(blf, &Kl[(nt * 16) * BQS + ks * 16], BQS);
                    wmma::mma_sync(sf[nt], ah, bhf, sf[nt]);
                    wmma::mma_sync(sf[nt], ah, blf, sf[nt]);
                    wmma::mma_sync(sf[nt], al, bhf, sf[nt]);
                }
            }
            #pragma unroll
            for (int nt = 0; nt < 4; nt++)
                wmma::store_matrix_sync(&Ss[(w * 16) * FQS + nt * 16], sf[nt], FQS, wmma::mem_row_major);
            __syncwarp();
        }

        // ---- online softmax on this warp's 16 rows ----
        {
            float* srow = &Ss[myrow * FQS + half * 32];
            float sv[32];
            float mx = -INFINITY;
            #pragma unroll
            for (int j = 0; j < 32; j++) { sv[j] = srow[j]; mx = fmaxf(mx, sv[j]); }
            mx = fmaxf(mx, __shfl_xor_sync(0xffffffffu, mx, 1));
            float mold = mrow[myrow];
            float mnew = fmaxf(mold, mx);
            float corr = __expf(mold - mnew);
            float sum = 0.0f;
            #pragma unroll
            for (int j = 0; j < 32; j++) {
                float e = __expf(sv[j] - mnew);
                sum += e;
                bf16 h, l;
                split_bf16(e, h, l);
                Ph[myrow * BQS + half * 32 + j] = h;
                Pl[myrow * BQS + half * 32 + j] = l;
            }
            sum += __shfl_xor_sync(0xffffffffu, sum, 1);
            if (half == 0) {
                lrow[myrow] = lrow[myrow] * corr + sum;
                mrow[myrow] = mnew;
                crow[myrow] = corr;
            }
            __syncwarp();
        }

        // ---- PV = P . V ----
        {
            wmma::fragment<wmma::accumulator, 16, 16, 16, float> pvf[4];
            #pragma unroll
            for (int nt = 0; nt < 4; nt++) wmma::fill_fragment(pvf[nt], 0.0f);
            #pragma unroll
            for (int ks = 0; ks < 4; ks++) {
                wmma::fragment<wmma::matrix_a, 16, 16, 16, bf16, wmma::row_major> ah, al;
                wmma::load_matrix_sync(ah, &Ph[(w * 16) * BQS + ks * 16], BQS);
                wmma::load_matrix_sync(al, &Pl[(w * 16) * BQS + ks * 16], BQS);
                #pragma unroll
                for (int nt = 0; nt < 4; nt++) {
                    wmma::fragment<wmma::matrix_b, 16, 16, 16, bf16, wmma::row_major> bhf, blf;
                    wmma::load_matrix_sync(bhf, &Vh[(ks * 16) * BQS + nt * 16], BQS);
                    wmma::load_matrix_sync(blf, &Vl[(ks * 16) * BQS + nt * 16], BQS);
                    wmma::mma_sync(pvf[nt], ah, bhf, pvf[nt]);
                    wmma::mma_sync(pvf[nt], ah, blf, pvf[nt]);
                    wmma::mma_sync(pvf[nt], al, bhf, pvf[nt]);
                }
            }
            #pragma unroll
            for (int nt = 0; nt < 4; nt++)
                wmma::store_matrix_sync(&Ss[(w * 16) * FQS + nt * 16], pvf[nt], FQS, wmma::mem_row_major);
            __syncwarp();
        }

        // ---- O = O * corr + PV ----
        #pragma unroll
        for (int i = 0; i < 32; i++) {
            int e = lane + 32 * i;
            int r = e >> 6, c = e & 63;
            int gr_ = w * 16 + r;
            Os[gr_ * FQS + c] = Os[gr_ * FQS + c] * crow[gr_] + Ss[gr_ * FQS + c];
        }
    }

    __syncthreads();
    // normalize + write O as bf16 hi/lo in proj-ready row-major [4096][1024]
    {
        int b = bh >> 4, h = bh & 15;     // bh = b*Hh + h
        bf16* ohE = (bf16*)g_oh4;
        bf16* olE = (bf16*)g_ol4;
        for (int i = 0; i < 32; i++) {
            int idx = tid + i * 256;       // 0..8191
            int row = idx >> 6, d = idx & 63;
            float v = Os[row * FQS + d] / lrow[row];
            size_t o = (size_t)(b * Nn + q0 + row) * Cc + h * HDd + d;
            bf16 hh, ll;
            split_bf16(v, hh, ll);
            ohE[o] = hh;
            olE[o] = ll;
        }
    }
}

// ---------------------------------------------------------------------------
extern "C" void kernel_launch(void* const* d_in, const int* in_sizes, int n_in,
                              void* d_out, int out_size) {
    const float* x      = (const float*)d_in[0];
    const float* w_qkv  = (const float*)d_in[1];
    const float* b_qkv  = (const float*)d_in[2];
    const float* gq     = (const float*)d_in[3];
    const float* beq    = (const float*)d_in[4];
    const float* gk     = (const float*)d_in[5];
    const float* bek    = (const float*)d_in[6];
    const float* w_proj = (const float*)d_in[7];
    const float* b_proj = (const float*)d_in[8];
    float* out = (float*)d_out;

    cudaFuncSetAttribute(attn_wmma, cudaFuncAttributeMaxDynamicSharedMemorySize, ATTN_SMEM);

    conv_kernel<<<2048, 256>>>(x,      0);
    conv_kernel<<<1536, 256>>>(w_qkv,  1);
    conv_kernel<<<512,  256>>>(w_proj, 2);
    gemm_wmma<<<dim3(3 * Cc / 128, ROWS / 128), 256>>>(b_qkv, nullptr, 1);
    ln_kernel<<<(2 * Bb * Hh * Nn) / 8, 256>>>(gq, beq, gk, bek);
    attn_wmma<<<dim3(Nn / 128, Bb * Hh), 256, ATTN_SMEM>>>();
    gemm_wmma<<<dim3(Cc / 128, ROWS / 128), 256>>>(b_proj, out, 0);
}